// round 6
// baseline (speedup 1.0000x reference)
#include <cuda_runtime.h>
#include <cstdint>

#define NVEH 16384
#define NT   256
#define H    20

#define VPC  64                 // vehicles per CTA
#define TPC  160                // 8 groups x 20 units
#define NCTA (NVEH / VPC)       // 256
#define VPT  8                  // vehicles per thread

typedef unsigned long long ull;

// Packed per-unit weights: unit u stride 48:
//   [0..19]  IF pairs for U rows (x0.5 prescale, sigmoid gates)
//   [20..22] IF pairs for W rows (x0.5)
//   [23]     IF bias (x0.5)
//   [24..43] GO pairs for U rows (g x1, o x0.5)
//   [44..46] GO pairs for W rows
//   [47]     GO bias
__device__ float2 gWt[20 * 48];
__device__ float  gWd[24];      // Wd[0..19], bd at [20]

// ---------- packed f32x2 helpers (sm_103a) ----------
__device__ __forceinline__ void ffma2(ull& d, ull a, ull b) {
    asm("fma.rn.f32x2 %0, %1, %2, %0;" : "+l"(d) : "l"(a), "l"(b));
}
__device__ __forceinline__ ull dup2(float x) {
    ull r; asm("mov.b64 %0, {%1, %1};" : "=l"(r) : "f"(x)); return r;
}
__device__ __forceinline__ float lo32(ull v) {
    float f; asm("{ .reg .b32 hi; mov.b64 {%0, hi}, %1; }" : "=f"(f) : "l"(v)); return f;
}
__device__ __forceinline__ float hi32(ull v) {
    float f; asm("{ .reg .b32 lo; mov.b64 {lo, %0}, %1; }" : "=f"(f) : "l"(v)); return f;
}

// ---------- HW tanh (MUFU.TANH) ----------
__device__ __forceinline__ float fast_tanh(float x) {
    float y; asm("tanh.approx.f32 %0, %1;" : "=f"(y) : "f"(x)); return y;
}
// gate weights pre-scaled by 0.5 -> sig(z) = 0.5*tanh(acc) + 0.5
__device__ __forceinline__ float sig_from_half(float acc_half) {
    return fmaf(0.5f, fast_tanh(acc_half), 0.5f);
}

// Bank-swizzled smem row offset (floats), 16B aligned.
__device__ __forceinline__ int rowoff(int v) {
    return v * 24 + ((v >> 2) & 1) * 4 + (v >> 3) * 8;
}

// ---------- repack kernel ----------
__global__ void repack_kernel(const float* __restrict__ W,
                              const float* __restrict__ U,
                              const float* __restrict__ b,
                              const float* __restrict__ Wd,
                              const float* __restrict__ bd)
{
    int i = blockIdx.x * blockDim.x + threadIdx.x;
    if (i < 20 * 48) {
        int u = i / 48, s = i % 48;
        float a0, a1;
        if (s < 24) {                       // IF pair
            const float* row = (s < 20) ? (U + s * 80)
                             : (s < 23) ? (W + (s - 20) * 80)
                             : b;
            a0 = 0.5f * row[u];             // i gate (sigmoid, prescaled)
            a1 = 0.5f * row[20 + u];        // f gate
        } else {                            // GO pair
            int k = s - 24;
            const float* row = (k < 20) ? (U + k * 80)
                             : (k < 23) ? (W + (k - 20) * 80)
                             : b;
            a0 = row[40 + u];               // g gate (tanh, full scale)
            a1 = 0.5f * row[60 + u];        // o gate
        }
        gWt[i] = make_float2(a0, a1);
    }
    if (i < 20)  gWd[i]  = Wd[i];
    if (i == 20) gWd[20] = bd[0];
}

__global__ __launch_bounds__(TPC, 2)
void rnncf_kernel(const float* __restrict__ lead_inputs,  // (NVEH, NT, 2)
                  const float* __restrict__ init_state,   // (NVEH, 2)
                  const float* __restrict__ h0,           // (NVEH, H)
                  const float* __restrict__ c0,           // (NVEH, H)
                  float* __restrict__ out,
                  int out_size)
{
    // Double-buffered rows: buf[p] holds (x(t), h(t)) for t&1 == p.
    // slots 0..2 = x, 3 = pad, 4+j = h[j]
    __shared__ float xh[2][1600];

    const int tid = threadIdx.x;
    const int u   = tid % 20;
    const int grp = tid / 20;
    const int vb  = grp * VPT;

    // ---- unit weights into registers (whole sim) ----
    ull wIF[23], wGO[23], bIF, bGO;
    {
        const ull* tb = reinterpret_cast<const ull*>(gWt) + u * 48;
#pragma unroll
        for (int k = 0; k < 23; ++k) { wIF[k] = tb[k]; wGO[k] = tb[24 + k]; }
        bIF = tb[23]; bGO = tb[47];
    }

    // ---- init ----
    float cc[VPT];
#pragma unroll
    for (int v = 0; v < VPT; ++v) {
        int gveh = blockIdx.x * VPC + vb + v;
        cc[v] = c0[gveh * H + u];
        xh[0][rowoff(vb + v) + 4 + u] = h0[gveh * H + u];
    }

    float pos = 0.f, spd = 0.f, bdv = 0.f;
    float wdr[20];
    const float2* mylead = nullptr;
    if (tid < VPC) {
        int gveh = blockIdx.x * VPC + tid;
        pos = init_state[2 * gveh];
        spd = init_state[2 * gveh + 1];
        mylead = reinterpret_cast<const float2*>(lead_inputs) + (size_t)gveh * NT;
        float2 l0 = mylead[0];
        int ro = rowoff(tid);
        xh[0][ro + 0] = (l0.x - pos) * (1.0f / 100.0f);
        xh[0][ro + 1] = spd * (1.0f / 40.0f);
        xh[0][ro + 2] = l0.y * (1.0f / 40.0f);
#pragma unroll
        for (int j = 0; j < 20; ++j) wdr[j] = gWd[j];
        bdv = gWd[20];
    }
    __syncthreads();

    const bool write_extras = (out_size >= NT * NVEH + NVEH + 2 * NVEH * H);
    float* outbase = out + blockIdx.x * VPC + tid;

    ull ai[VPT], ag[VPT];

    // One U-row slot: h value broadcast, two packed FMAs
#define KH(kk, val, vv)                                    \
    { ull md = dup2(val);                                  \
      ffma2(ai[vv], wIF[kk], md);                          \
      ffma2(ag[vv], wGO[kk], md); }

    // ---- prologue "P1": acc = b + U*h(0) ----
#pragma unroll 2
    for (int v = 0; v < VPT; ++v) {
        const int ro = rowoff(vb + v);
        const float* rb = xh[0];
        float4 r1 = *reinterpret_cast<const float4*>(rb + ro + 4);
        float4 r2 = *reinterpret_cast<const float4*>(rb + ro + 8);
        float4 r3 = *reinterpret_cast<const float4*>(rb + ro + 12);
        float4 r4 = *reinterpret_cast<const float4*>(rb + ro + 16);
        float4 r5 = *reinterpret_cast<const float4*>(rb + ro + 20);
        ai[v] = bIF; ag[v] = bGO;
        KH(0, r1.x, v) KH(1, r1.y, v) KH(2, r1.z, v) KH(3, r1.w, v)
        KH(4, r2.x, v) KH(5, r2.y, v) KH(6, r2.z, v) KH(7, r2.w, v)
        KH(8, r3.x, v) KH(9, r3.y, v) KH(10, r3.z, v) KH(11, r3.w, v)
        KH(12, r4.x, v) KH(13, r4.y, v) KH(14, r4.z, v) KH(15, r4.w, v)
        KH(16, r5.x, v) KH(17, r5.y, v) KH(18, r5.z, v) KH(19, r5.w, v)
    }

#pragma unroll 1
    for (int t = 0; t < NT; ++t) {
        const float* rb = xh[t & 1];
        float*       wb = xh[(t + 1) & 1];

        // driver lead prefetch for x(t+1)
        float2 nl = make_float2(0.f, 0.f);
        if (tid < VPC) {
            int tn = (t + 1 < NT) ? (t + 1) : (NT - 1);
            nl = mylead[tn];
        }

        // ---- P2: acc += W*x(t); gates; write h(t+1) ----
#pragma unroll 4
        for (int v = 0; v < VPT; ++v) {
            const int ro = rowoff(vb + v);
            float4 r0 = *reinterpret_cast<const float4*>(rb + ro);
            KH(20, r0.x, v) KH(21, r0.y, v) KH(22, r0.z, v)

            float si = sig_from_half(lo32(ai[v]));
            float sf = sig_from_half(hi32(ai[v]));
            float tg = fast_tanh(lo32(ag[v]));
            float so = sig_from_half(hi32(ag[v]));
            float cn = fmaf(sf, cc[v], si * tg);
            cc[v] = cn;
            wb[ro + 4 + u] = so * fast_tanh(cn);    // h(t+1)
        }
        __syncthreads();

        // ---- P1: drivers do scalar chain; all threads do U*h(t+1) ----
        if (tid < VPC) {
            const int ro = rowoff(tid);
            float4 a0 = *reinterpret_cast<const float4*>(wb + ro + 4);
            float4 a1 = *reinterpret_cast<const float4*>(wb + ro + 8);
            float4 a2 = *reinterpret_cast<const float4*>(wb + ro + 12);
            float4 a3 = *reinterpret_cast<const float4*>(wb + ro + 16);
            float4 a4 = *reinterpret_cast<const float4*>(wb + ro + 20);
            float p0 = bdv, p1 = 0.f, p2 = 0.f, p3 = 0.f;
            p0 = fmaf(a0.x, wdr[0],  p0); p1 = fmaf(a0.y, wdr[1],  p1);
            p2 = fmaf(a0.z, wdr[2],  p2); p3 = fmaf(a0.w, wdr[3],  p3);
            p0 = fmaf(a1.x, wdr[4],  p0); p1 = fmaf(a1.y, wdr[5],  p1);
            p2 = fmaf(a1.z, wdr[6],  p2); p3 = fmaf(a1.w, wdr[7],  p3);
            p0 = fmaf(a2.x, wdr[8],  p0); p1 = fmaf(a2.y, wdr[9],  p1);
            p2 = fmaf(a2.z, wdr[10], p2); p3 = fmaf(a2.w, wdr[11], p3);
            p0 = fmaf(a3.x, wdr[12], p0); p1 = fmaf(a3.y, wdr[13], p1);
            p2 = fmaf(a3.z, wdr[14], p2); p3 = fmaf(a3.w, wdr[15], p3);
            p0 = fmaf(a4.x, wdr[16], p0); p1 = fmaf(a4.y, wdr[17], p1);
            p2 = fmaf(a4.z, wdr[18], p2); p3 = fmaf(a4.w, wdr[19], p3);
            float p = (p0 + p1) + (p2 + p3);

            float a = fmaf(7.0f, p, -4.0f);          // (MAXA-MINA)*out + MINA
            spd = fmaf(0.1f, a, spd);
            pos = fmaf(0.1f, a, pos);
            outbase[(size_t)t * NVEH] = pos;
            wb[rowoff(tid) + 0] = (nl.x - pos) * (1.0f / 100.0f);
            wb[rowoff(tid) + 1] = spd * (1.0f / 40.0f);
            wb[rowoff(tid) + 2] = nl.y * (1.0f / 40.0f);
        }

        if (t < NT - 1) {
#pragma unroll 2
            for (int v = 0; v < VPT; ++v) {
                const int ro = rowoff(vb + v);
                float4 r1 = *reinterpret_cast<const float4*>(wb + ro + 4);
                float4 r2 = *reinterpret_cast<const float4*>(wb + ro + 8);
                float4 r3 = *reinterpret_cast<const float4*>(wb + ro + 12);
                float4 r4 = *reinterpret_cast<const float4*>(wb + ro + 16);
                float4 r5 = *reinterpret_cast<const float4*>(wb + ro + 20);
                ai[v] = bIF; ag[v] = bGO;
                KH(0, r1.x, v) KH(1, r1.y, v) KH(2, r1.z, v) KH(3, r1.w, v)
                KH(4, r2.x, v) KH(5, r2.y, v) KH(6, r2.z, v) KH(7, r2.w, v)
                KH(8, r3.x, v) KH(9, r3.y, v) KH(10, r3.z, v) KH(11, r3.w, v)
                KH(12, r4.x, v) KH(13, r4.y, v) KH(14, r4.z, v) KH(15, r4.w, v)
                KH(16, r5.x, v) KH(17, r5.y, v) KH(18, r5.z, v) KH(19, r5.w, v)
            }
        }
        __syncthreads();
    }
#undef KH

    if (write_extras) {
        if (tid < VPC)
            out[(size_t)NT * NVEH + blockIdx.x * VPC + tid] = spd;
        float* hout = out + (size_t)NT * NVEH + NVEH;
        float* cout = hout + (size_t)NVEH * H;
        const float* fb = xh[0];    // h(256) lives in buf[(255+1)&1] = buf0
#pragma unroll
        for (int v = 0; v < VPT; ++v) {
            int gveh = blockIdx.x * VPC + vb + v;
            hout[gveh * H + u] = fb[rowoff(vb + v) + 4 + u];
            cout[gveh * H + u] = cc[v];
        }
    }
}

extern "C" void kernel_launch(void* const* d_in, const int* in_sizes, int n_in,
                              void* d_out, int out_size) {
    const float* lead_inputs = (const float*)d_in[0];
    const float* init_state  = (const float*)d_in[1];
    const float* h0          = (const float*)d_in[2];
    const float* c0          = (const float*)d_in[3];
    const float* W           = (const float*)d_in[4];
    const float* U           = (const float*)d_in[5];
    const float* b           = (const float*)d_in[6];
    const float* Wd          = (const float*)d_in[7];
    const float* bd          = (const float*)d_in[8];

    repack_kernel<<<1, 1024>>>(W, U, b, Wd, bd);
    rnncf_kernel<<<NCTA, TPC>>>(lead_inputs, init_state, h0, c0,
                                (float*)d_out, out_size);
}